// round 3
// baseline (speedup 1.0000x reference)
#include <cuda_runtime.h>
#include <cuda_fp16.h>
#include <cstdint>

// ----------------------------------------------------------------------------
// WindowAttention fused kernel (B200 / sm_100a), round 3 resubmit (infra retry)
//   inputs  [4096, 64, 192] f32
//   mask    [64, 64, 64]    f32 (additive)
//   w_qkv   [192, 576] f32, b_qkv [576]
//   bias_table [225, 6] f32
//   w_proj  [192, 192] f32, b_proj [192]
//   out     [4096, 64, 192] f32
// One CTA = 2 windows (128 tokens). Fully fused: QKV GEMM -> attention -> proj.
// ----------------------------------------------------------------------------

#define N_TOK      64
#define C_DIM      192
#define N_HEADS    6
#define HEAD_DIM   32
#define WPB        2            // windows per block
#define M_TILE     (WPB * N_TOK)   // 128
#define NUM_WINS   64
#define SCALE_F    0.07216878364870323f   // 192^-0.5

// smem layout (in halves)
#define XS_OFF     0
#define XS_STR     200          // 192 + 8 pad  (row stride 100 words = +4 banks)
#define QKV_OFF    (128 * 200)              // 25600
#define QKV_STR    584          // 576 + 8 pad (292 words = +4 banks)
#define WT_OFF     (QKV_OFF + 128 * 584)    // 100352
#define WT_STR     200
#define MASK_STR   72           // padded mask row (36 words = +4 banks)
#define SMEM_HALVES (WT_OFF + 64 * 200)     // 113152
#define SMEM_BYTES  (SMEM_HALVES * 2)       // 226304 (< 227KB cap)

// Preprocessed weights / bias (device globals: no allocation allowed)
__device__ __half g_wq_t[576 * 192];   // w_qkv transposed [n][k], fp16
__device__ __half g_wp_t[192 * 192];   // w_proj transposed [n][k], fp16
__device__ __half g_relb[N_HEADS * 64 * 64];  // rel-pos bias gathered [h][i][j], fp16

// ---------------------------------------------------------------- prepasses
__global__ void prep_wq(const float* __restrict__ wq) {
    int i = blockIdx.x * 256 + threadIdx.x;
    if (i < 576 * 192) {
        int n = i / 192, k = i % 192;
        g_wq_t[n * 192 + k] = __float2half_rn(wq[k * 576 + n]);
    }
}
__global__ void prep_wp(const float* __restrict__ wp) {
    int i = blockIdx.x * 256 + threadIdx.x;
    if (i < 192 * 192) {
        int n = i / 192, k = i % 192;
        g_wp_t[n * 192 + k] = __float2half_rn(wp[k * 192 + n]);
    }
}
__global__ void prep_relb(const float* __restrict__ bt) {
    int i = blockIdx.x * 256 + threadIdx.x;
    if (i < N_HEADS * 64 * 64) {
        int h = i >> 12;
        int ij = i & 4095;
        int r = ij >> 6, c = ij & 63;
        int idx = ((r >> 3) - (c >> 3) + 7) * 15 + ((r & 7) - (c & 7) + 7);
        g_relb[i] = __float2half_rn(bt[idx * 6 + h]);
    }
}

// ---------------------------------------------------------------- helpers
__device__ __forceinline__ uint32_t f22u(float a, float b) {
    __half2 h = __floats2half2_rn(a, b);   // .x = a (low), .y = b (high)
    return *reinterpret_cast<uint32_t*>(&h);
}
__device__ __forceinline__ uint32_t pack_hh(__half a, __half b) {
    __half2 h = __halves2half2(a, b);
    return *reinterpret_cast<uint32_t*>(&h);
}

__device__ __forceinline__ void mma16816(float c[4], const uint32_t a[4], const uint32_t b[2]) {
    asm volatile(
        "mma.sync.aligned.m16n8k16.row.col.f32.f16.f16.f32 "
        "{%0,%1,%2,%3}, {%4,%5,%6,%7}, {%8,%9}, {%0,%1,%2,%3};\n"
        : "+f"(c[0]), "+f"(c[1]), "+f"(c[2]), "+f"(c[3])
        : "r"(a[0]), "r"(a[1]), "r"(a[2]), "r"(a[3]), "r"(b[0]), "r"(b[1]));
}

// block GEMM: [128, 64] += A[128, 192] (smem, stride XS_STR) * Wt[64, 192]^T
// 8 warps as 4(m) x 2(n); warp tile 32x32.
__device__ __forceinline__ void gemm_128x64_k192(const __half* sm, int a_off,
                                                 float acc[2][4][4]) {
    const int lane = threadIdx.x & 31;
    const int w    = threadIdx.x >> 5;
    const int wm = w & 3, wn = w >> 2;
    const int qr = lane >> 2, qc = (lane & 3) * 2;

#pragma unroll
    for (int mt = 0; mt < 2; mt++)
#pragma unroll
        for (int nt = 0; nt < 4; nt++)
#pragma unroll
            for (int e = 0; e < 4; e++) acc[mt][nt][e] = 0.f;

#pragma unroll
    for (int ks = 0; ks < 12; ks++) {
        const int k0 = ks * 16;
        uint32_t a[2][4], b[4][2];
#pragma unroll
        for (int mt = 0; mt < 2; mt++) {
            int r = wm * 32 + mt * 16 + qr;
            const __half* base = sm + a_off + r * XS_STR + k0 + qc;
            a[mt][0] = *(const uint32_t*)(base);
            a[mt][1] = *(const uint32_t*)(base + 8 * XS_STR);
            a[mt][2] = *(const uint32_t*)(base + 8);
            a[mt][3] = *(const uint32_t*)(base + 8 * XS_STR + 8);
        }
#pragma unroll
        for (int nt = 0; nt < 4; nt++) {
            int n = wn * 32 + nt * 8 + qr;
            const __half* base = sm + WT_OFF + n * WT_STR + k0 + qc;
            b[nt][0] = *(const uint32_t*)(base);
            b[nt][1] = *(const uint32_t*)(base + 8);
        }
#pragma unroll
        for (int mt = 0; mt < 2; mt++)
#pragma unroll
            for (int nt = 0; nt < 4; nt++) mma16816(acc[mt][nt], a[mt], b[nt]);
    }
}

__device__ __forceinline__ void load_wt(__half* sm, const __half* __restrict__ src,
                                        int rowbase) {
    // 64 rows x 192 halves, 16B vectors (both sides 16B-aligned)
    for (int i = threadIdx.x; i < 64 * 24; i += 256) {
        int n = i / 24, k8 = i % 24;
        uint4 v = *(const uint4*)(src + (rowbase + n) * 192 + k8 * 8);
        *(uint4*)(sm + WT_OFF + n * WT_STR + k8 * 8) = v;
    }
}

// attention for one (local window, head) pair; whole 64x64 tile in one warp
__device__ __forceinline__ void attn_pair(__half* sm, int lw, int h) {
    const int lane = threadIdx.x & 31;
    const int qr = lane >> 2, qc = (lane & 3) * 2;
    const int tokbase = lw * 64;
    const int qb = h * 32, kb = 192 + h * 32, vb = 384 + h * 32;

    // packed unnormalized P (fp16) + per-row normalizers
    uint32_t p[4][8][2];
    float invA[4], invB[4];

    {
        float s[4][8][4];
#pragma unroll
        for (int mt = 0; mt < 4; mt++)
#pragma unroll
            for (int nt = 0; nt < 8; nt++)
#pragma unroll
                for (int e = 0; e < 4; e++) s[mt][nt][e] = 0.f;

        // S = Q @ K^T   (K dim = 32 => 2 k-steps)
#pragma unroll
        for (int ks = 0; ks < 2; ks++) {
            const int k0 = ks * 16;
            uint32_t a[4][4], b[8][2];
#pragma unroll
            for (int mt = 0; mt < 4; mt++) {
                int r = tokbase + mt * 16 + qr;
                const __half* base = sm + QKV_OFF + r * QKV_STR + qb + k0 + qc;
                a[mt][0] = *(const uint32_t*)(base);
                a[mt][1] = *(const uint32_t*)(base + 8 * QKV_STR);
                a[mt][2] = *(const uint32_t*)(base + 8);
                a[mt][3] = *(const uint32_t*)(base + 8 * QKV_STR + 8);
            }
#pragma unroll
            for (int nt = 0; nt < 8; nt++) {
                int n = tokbase + nt * 8 + qr;
                const __half* base = sm + QKV_OFF + n * QKV_STR + kb + k0 + qc;
                b[nt][0] = *(const uint32_t*)(base);
                b[nt][1] = *(const uint32_t*)(base + 8);
            }
#pragma unroll
            for (int mt = 0; mt < 4; mt++)
#pragma unroll
                for (int nt = 0; nt < 8; nt++) mma16816(s[mt][nt], a[mt], b[nt]);
        }

        // scale + rel-pos bias + shift mask, row softmax, pack to fp16.
        // Rows of a quad live in lanes qr*4+{0..3}; shfl.xor 1,2 reduces them.
#pragma unroll
        for (int mt = 0; mt < 4; mt++) {
            const int iA = mt * 16 + qr, iB = iA + 8;
            float mA = -1e30f, mB = -1e30f;
#pragma unroll
            for (int nt = 0; nt < 8; nt++) {
                const int j = nt * 8 + qc;
                float2 rA = __half22float2(*(const __half2*)(g_relb + h * 4096 + iA * 64 + j));
                float2 rB = __half22float2(*(const __half2*)(g_relb + h * 4096 + iB * 64 + j));
                float2 kA = __half22float2(*(const __half2*)(sm + WT_OFF + lw * (MASK_STR * 64) + iA * MASK_STR + j));
                float2 kB = __half22float2(*(const __half2*)(sm + WT_OFF + lw * (MASK_STR * 64) + iB * MASK_STR + j));
                s[mt][nt][0] = s[mt][nt][0] * SCALE_F + rA.x + kA.x;
                s[mt][nt][1] = s[mt][nt][1] * SCALE_F + rA.y + kA.y;
                s[mt][nt][2] = s[mt][nt][2] * SCALE_F + rB.x + kB.x;
                s[mt][nt][3] = s[mt][nt][3] * SCALE_F + rB.y + kB.y;
                mA = fmaxf(mA, fmaxf(s[mt][nt][0], s[mt][nt][1]));
                mB = fmaxf(mB, fmaxf(s[mt][nt][2], s[mt][nt][3]));
            }
            mA = fmaxf(mA, __shfl_xor_sync(0xffffffffu, mA, 1));
            mA = fmaxf(mA, __shfl_xor_sync(0xffffffffu, mA, 2));
            mB = fmaxf(mB, __shfl_xor_sync(0xffffffffu, mB, 1));
            mB = fmaxf(mB, __shfl_xor_sync(0xffffffffu, mB, 2));
            float sA = 0.f, sB = 0.f;
#pragma unroll
            for (int nt = 0; nt < 8; nt++) {
                float e0 = __expf(s[mt][nt][0] - mA);
                float e1 = __expf(s[mt][nt][1] - mA);
                float e2 = __expf(s[mt][nt][2] - mB);
                float e3 = __expf(s[mt][nt][3] - mB);
                sA += e0 + e1;
                sB += e2 + e3;
                // pack unnormalized P now -> s[mt] registers die here
                p[mt][nt][0] = f22u(e0, e1);
                p[mt][nt][1] = f22u(e2, e3);
            }
            sA += __shfl_xor_sync(0xffffffffu, sA, 1);
            sA += __shfl_xor_sync(0xffffffffu, sA, 2);
            sB += __shfl_xor_sync(0xffffffffu, sB, 1);
            sB += __shfl_xor_sync(0xffffffffu, sB, 2);
            invA[mt] = 1.f / sA;
            invB[mt] = 1.f / sB;
        }
    }

    // O = P @ V  (P = unnormalized exp in fp16, normalize in fp32 at the end)
    float o[4][4][4];
#pragma unroll
    for (int mt = 0; mt < 4; mt++)
#pragma unroll
        for (int nd = 0; nd < 4; nd++)
#pragma unroll
            for (int e = 0; e < 4; e++) o[mt][nd][e] = 0.f;

#pragma unroll
    for (int kt = 0; kt < 4; kt++) {
        uint32_t bv[4][2];
#pragma unroll
        for (int nd = 0; nd < 4; nd++) {
            const int d = vb + nd * 8 + qr;
            const int j0 = tokbase + kt * 16 + qc;
            __half v0 = sm[QKV_OFF + (j0    ) * QKV_STR + d];
            __half v1 = sm[QKV_OFF + (j0 + 1) * QKV_STR + d];
            __half v2 = sm[QKV_OFF + (j0 + 8) * QKV_STR + d];
            __half v3 = sm[QKV_OFF + (j0 + 9) * QKV_STR + d];
            bv[nd][0] = pack_hh(v0, v1);
            bv[nd][1] = pack_hh(v2, v3);
        }
#pragma unroll
        for (int mt = 0; mt < 4; mt++) {
            uint32_t a[4];
            a[0] = p[mt][2 * kt][0];
            a[1] = p[mt][2 * kt][1];
            a[2] = p[mt][2 * kt + 1][0];
            a[3] = p[mt][2 * kt + 1][1];
#pragma unroll
            for (int nd = 0; nd < 4; nd++) mma16816(o[mt][nd], a, bv[nd]);
        }
    }

    // write O (normalized) into the freed X buffer as fp16 [128][192]
#pragma unroll
    for (int mt = 0; mt < 4; mt++)
#pragma unroll
        for (int nd = 0; nd < 4; nd++) {
            const int rA = tokbase + mt * 16 + qr;
            const int col = h * 32 + nd * 8 + qc;
            *(uint32_t*)&sm[XS_OFF + rA * XS_STR + col] =
                f22u(o[mt][nd][0] * invA[mt], o[mt][nd][1] * invA[mt]);
            *(uint32_t*)&sm[XS_OFF + (rA + 8) * XS_STR + col] =
                f22u(o[mt][nd][2] * invB[mt], o[mt][nd][3] * invB[mt]);
        }
}

// ---------------------------------------------------------------- main kernel
__global__ void __launch_bounds__(256, 1)
wa_main(const float* __restrict__ X, const float* __restrict__ mask,
        const float* __restrict__ b_qkv, const float* __restrict__ b_proj,
        float* __restrict__ out) {
    extern __shared__ __half sm[];
    const int tid = threadIdx.x;
    const int lane = tid & 31;
    const int w = tid >> 5;
    const int wm = w & 3, wn = w >> 2;
    const int qr = lane >> 2, qc = (lane & 3) * 2;
    const int cta = blockIdx.x;

    // ---- Phase A: load X tile [128, 192] -> smem fp16
    {
        const float4* xin = (const float4*)(X + (size_t)cta * M_TILE * C_DIM);
        for (int i = tid; i < M_TILE * 48; i += 256) {
            int row = i / 48, c4 = i % 48;
            float4 v = xin[row * 48 + c4];
            int o = XS_OFF + row * XS_STR + c4 * 4;
            *(uint32_t*)&sm[o]     = f22u(v.x, v.y);
            *(uint32_t*)&sm[o + 2] = f22u(v.z, v.w);
        }
    }

    // ---- Phase B: QKV GEMM in 9 chunks of 64 output columns
    for (int chunk = 0; chunk < 9; chunk++) {
        __syncthreads();
        load_wt(sm, g_wq_t, chunk * 64);
        __syncthreads();
        float acc[2][4][4];
        gemm_128x64_k192(sm, XS_OFF, acc);
        const int cbase = chunk * 64;
#pragma unroll
        for (int mt = 0; mt < 2; mt++)
#pragma unroll
            for (int nt = 0; nt < 4; nt++) {
                const int row = wm * 32 + mt * 16 + qr;
                const int col = cbase + wn * 32 + nt * 8 + qc;
                const float b0 = b_qkv[col], b1 = b_qkv[col + 1];
                *(uint32_t*)&sm[QKV_OFF + row * QKV_STR + col] =
                    f22u(acc[mt][nt][0] + b0, acc[mt][nt][1] + b1);
                *(uint32_t*)&sm[QKV_OFF + (row + 8) * QKV_STR + col] =
                    f22u(acc[mt][nt][2] + b0, acc[mt][nt][3] + b1);
            }
    }
    __syncthreads();

    // ---- Phase C: stage shift masks for the 2 windows (fp16, padded rows)
    {
        const int w0 = (cta * WPB) & (NUM_WINS - 1);
        const int w1 = (cta * WPB + 1) & (NUM_WINS - 1);
        for (int i = tid; i < 2 * 4096; i += 256) {
            int lw = i >> 12, idx = i & 4095;
            int r = idx >> 6, c = idx & 63;
            int wmask = lw ? w1 : w0;
            sm[WT_OFF + lw * (MASK_STR * 64) + r * MASK_STR + c] =
                __float2half_rn(mask[wmask * 4096 + idx]);
        }
    }
    __syncthreads();

    // ---- attention: 12 (window, head) pairs over 8 warps
    for (int it = 0; it < 2; it++) {
        int p = w + it * 8;
        if (p < WPB * N_HEADS) {
            attn_pair(sm, p / N_HEADS, p % N_HEADS);
        }
    }
    __syncthreads();

    // ---- Phase D: proj GEMM in 3 chunks of 64 output columns -> gmem
    for (int chunk = 0; chunk < 3; chunk++) {
        __syncthreads();
        load_wt(sm, g_wp_t, chunk * 64);
        __syncthreads();
        float acc[2][4][4];
        gemm_128x64_k192(sm, XS_OFF, acc);
        const int cbase = chunk * 64;
#pragma unroll
        for (int mt = 0; mt < 2; mt++)
#pragma unroll
            for (int nt = 0; nt < 4; nt++) {
                const int row = wm * 32 + mt * 16 + qr;
                const int col = cbase + wn * 32 + nt * 8 + qc;
                const float b0 = b_proj[col], b1 = b_proj[col + 1];
                const size_t t0 = (size_t)cta * M_TILE + row;
                float2 v0 = {acc[mt][nt][0] + b0, acc[mt][nt][1] + b1};
                float2 v1 = {acc[mt][nt][2] + b0, acc[mt][nt][3] + b1};
                *(float2*)&out[t0 * C_DIM + col]       = v0;
                *(float2*)&out[(t0 + 8) * C_DIM + col] = v1;
            }
    }
}

// ---------------------------------------------------------------- launch
extern "C" void kernel_launch(void* const* d_in, const int* in_sizes, int n_in,
                              void* d_out, int out_size) {
    const float* inputs     = (const float*)d_in[0];
    const float* mask       = (const float*)d_in[1];
    const float* w_qkv      = (const float*)d_in[2];
    const float* b_qkv      = (const float*)d_in[3];
    const float* bias_table = (const float*)d_in[4];
    const float* w_proj     = (const float*)d_in[5];
    const float* b_proj     = (const float*)d_in[6];
    float* out = (float*)d_out;

    prep_wq<<<(576 * 192 + 255) / 256, 256>>>(w_qkv);
    prep_wp<<<(192 * 192 + 255) / 256, 256>>>(w_proj);
    prep_relb<<<(N_HEADS * 64 * 64 + 255) / 256, 256>>>(bias_table);

    cudaFuncSetAttribute(wa_main, cudaFuncAttributeMaxDynamicSharedMemorySize,
                         SMEM_BYTES);
    wa_main<<<4096 / WPB, 256, SMEM_BYTES>>>(inputs, mask, b_qkv, b_proj, out);
}

// round 6
// speedup vs baseline: 1.0073x; 1.0073x over previous
#include <cuda_runtime.h>
#include <cuda_fp16.h>
#include <cstdint>

// ----------------------------------------------------------------------------
// WindowAttention fused kernel (B200 / sm_100a), round 6 resubmit (infra retry)
// One CTA = 2 windows (128 tokens), 16 warps / 512 threads. Fully fused.
//   GEMMs: 16 warps as 4m x 4n (warp tile 32x16)
//   Attention: 24 half-tile tasks (32x64) over 16 warps
// ----------------------------------------------------------------------------

#define N_TOK      64
#define C_DIM      192
#define N_HEADS    6
#define WPB        2
#define M_TILE     (WPB * N_TOK)   // 128
#define NUM_WINS   64
#define NTHREADS   512
#define SCALE_F    0.07216878364870323f   // 192^-0.5

// smem layout (in halves)
#define XS_OFF     0
#define XS_STR     200
#define QKV_OFF    (128 * 200)              // 25600
#define QKV_STR    584
#define WT_OFF     (QKV_OFF + 128 * 584)    // 100352
#define WT_STR     200
#define MASK_STR   72
#define SMEM_HALVES (WT_OFF + 64 * 200)     // 113152
#define SMEM_BYTES  (SMEM_HALVES * 2)       // 226304

__device__ __half g_wq_t[576 * 192];
__device__ __half g_wp_t[192 * 192];
__device__ __half g_relb[N_HEADS * 64 * 64];

// ---------------------------------------------------------------- prepasses
__global__ void prep_wq(const float* __restrict__ wq) {
    int i = blockIdx.x * 256 + threadIdx.x;
    if (i < 576 * 192) {
        int n = i / 192, k = i % 192;
        g_wq_t[n * 192 + k] = __float2half_rn(wq[k * 576 + n]);
    }
}
__global__ void prep_wp(const float* __restrict__ wp) {
    int i = blockIdx.x * 256 + threadIdx.x;
    if (i < 192 * 192) {
        int n = i / 192, k = i % 192;
        g_wp_t[n * 192 + k] = __float2half_rn(wp[k * 192 + n]);
    }
}
__global__ void prep_relb(const float* __restrict__ bt) {
    int i = blockIdx.x * 256 + threadIdx.x;
    if (i < N_HEADS * 64 * 64) {
        int h = i >> 12;
        int ij = i & 4095;
        int r = ij >> 6, c = ij & 63;
        int idx = ((r >> 3) - (c >> 3) + 7) * 15 + ((r & 7) - (c & 7) + 7);
        g_relb[i] = __float2half_rn(bt[idx * 6 + h]);
    }
}

// ---------------------------------------------------------------- helpers
__device__ __forceinline__ uint32_t f22u(float a, float b) {
    __half2 h = __floats2half2_rn(a, b);
    return *reinterpret_cast<uint32_t*>(&h);
}
__device__ __forceinline__ uint32_t pack_hh(__half a, __half b) {
    __half2 h = __halves2half2(a, b);
    return *reinterpret_cast<uint32_t*>(&h);
}

__device__ __forceinline__ void mma16816(float c[4], const uint32_t a[4], const uint32_t b[2]) {
    asm volatile(
        "mma.sync.aligned.m16n8k16.row.col.f32.f16.f16.f32 "
        "{%0,%1,%2,%3}, {%4,%5,%6,%7}, {%8,%9}, {%0,%1,%2,%3};\n"
        : "+f"(c[0]), "+f"(c[1]), "+f"(c[2]), "+f"(c[3])
        : "r"(a[0]), "r"(a[1]), "r"(a[2]), "r"(a[3]), "r"(b[0]), "r"(b[1]));
}

// block GEMM: [128, 64] = A[128,192](smem XS) * Wt[64,192]^T (smem WT)
// 16 warps as 4(m) x 4(n); warp tile 32x16. acc[2][2][4].
__device__ __forceinline__ void gemm_128x64_k192(const __half* sm, float acc[2][2][4]) {
    const int lane = threadIdx.x & 31;
    const int w    = threadIdx.x >> 5;
    const int wm = w & 3, wn = w >> 2;
    const int qr = lane >> 2, qc = (lane & 3) * 2;

#pragma unroll
    for (int mt = 0; mt < 2; mt++)
#pragma unroll
        for (int nt = 0; nt < 2; nt++)
#pragma unroll
            for (int e = 0; e < 4; e++) acc[mt][nt][e] = 0.f;

#pragma unroll
    for (int ks = 0; ks < 12; ks++) {
        const int k0 = ks * 16;
        uint32_t a[2][4], b[2][2];
#pragma unroll
        for (int mt = 0; mt < 2; mt++) {
            int r = wm * 32 + mt * 16 + qr;
            const __half* base = sm + XS_OFF + r * XS_STR + k0 + qc;
            a[mt][0] = *(const uint32_t*)(base);
            a[mt][1] = *(const uint32_t*)(base + 8 * XS_STR);
            a[mt][2] = *(const uint32_t*)(base + 8);
            a[mt][3] = *(const uint32_t*)(base + 8 * XS_STR + 8);
        }
#pragma unroll
        for (int nt = 0; nt < 2; nt++) {
            int n = wn * 16 + nt * 8 + qr;
            const __half* base = sm + WT_OFF + n * WT_STR + k0 + qc;
            b[nt][0] = *(const uint32_t*)(base);
            b[nt][1] = *(const uint32_t*)(base + 8);
        }
#pragma unroll
        for (int mt = 0; mt < 2; mt++)
#pragma unroll
            for (int nt = 0; nt < 2; nt++) mma16816(acc[mt][nt], a[mt], b[nt]);
    }
}

__device__ __forceinline__ void load_wt(__half* sm, const __half* __restrict__ src,
                                        int rowbase) {
    for (int i = threadIdx.x; i < 64 * 24; i += NTHREADS) {
        int n = i / 24, k8 = i % 24;
        uint4 v = *(const uint4*)(src + (rowbase + n) * 192 + k8 * 8);
        *(uint4*)(sm + WT_OFF + n * WT_STR + k8 * 8) = v;
    }
}

// attention half-tile: rows [mhalf*32, mhalf*32+32) of the 64x64 score tile
// for (local window lw, head h). One warp per task.
__device__ __forceinline__ void attn_half(__half* sm, int lw, int h, int mhalf) {
    const int lane = threadIdx.x & 31;
    const int qr = lane >> 2, qc = (lane & 3) * 2;
    const int tokbase = lw * 64;
    const int rowbase = tokbase + mhalf * 32;       // global token row of frag 0
    const int qb = h * 32, kb = 192 + h * 32, vb = 384 + h * 32;

    uint32_t p[2][8][2];
    float invA[2], invB[2];

    {
        float s[2][8][4];
#pragma unroll
        for (int mt = 0; mt < 2; mt++)
#pragma unroll
            for (int nt = 0; nt < 8; nt++)
#pragma unroll
                for (int e = 0; e < 4; e++) s[mt][nt][e] = 0.f;

        // S = Q @ K^T (head dim 32 => 2 k-steps)
#pragma unroll
        for (int ks = 0; ks < 2; ks++) {
            const int k0 = ks * 16;
            uint32_t a[2][4], b[8][2];
#pragma unroll
            for (int mt = 0; mt < 2; mt++) {
                int r = rowbase + mt * 16 + qr;
                const __half* base = sm + QKV_OFF + r * QKV_STR + qb + k0 + qc;
                a[mt][0] = *(const uint32_t*)(base);
                a[mt][1] = *(const uint32_t*)(base + 8 * QKV_STR);
                a[mt][2] = *(const uint32_t*)(base + 8);
                a[mt][3] = *(const uint32_t*)(base + 8 * QKV_STR + 8);
            }
#pragma unroll
            for (int nt = 0; nt < 8; nt++) {
                int n = tokbase + nt * 8 + qr;
                const __half* base = sm + QKV_OFF + n * QKV_STR + kb + k0 + qc;
                b[nt][0] = *(const uint32_t*)(base);
                b[nt][1] = *(const uint32_t*)(base + 8);
            }
#pragma unroll
            for (int mt = 0; mt < 2; mt++)
#pragma unroll
                for (int nt = 0; nt < 8; nt++) mma16816(s[mt][nt], a[mt], b[nt]);
        }

        // scale + rel bias + shift mask, softmax, pack P fp16
#pragma unroll
        for (int mt = 0; mt < 2; mt++) {
            const int iA = mhalf * 32 + mt * 16 + qr, iB = iA + 8;  // local row in 64x64 tile
            float mA = -1e30f, mB = -1e30f;
#pragma unroll
            for (int nt = 0; nt < 8; nt++) {
                const int j = nt * 8 + qc;
                float2 rA = __half22float2(*(const __half2*)(g_relb + h * 4096 + iA * 64 + j));
                float2 rB = __half22float2(*(const __half2*)(g_relb + h * 4096 + iB * 64 + j));
                float2 kA = __half22float2(*(const __half2*)(sm + WT_OFF + lw * (MASK_STR * 64) + iA * MASK_STR + j));
                float2 kB = __half22float2(*(const __half2*)(sm + WT_OFF + lw * (MASK_STR * 64) + iB * MASK_STR + j));
                s[mt][nt][0] = s[mt][nt][0] * SCALE_F + rA.x + kA.x;
                s[mt][nt][1] = s[mt][nt][1] * SCALE_F + rA.y + kA.y;
                s[mt][nt][2] = s[mt][nt][2] * SCALE_F + rB.x + kB.x;
                s[mt][nt][3] = s[mt][nt][3] * SCALE_F + rB.y + kB.y;
                mA = fmaxf(mA, fmaxf(s[mt][nt][0], s[mt][nt][1]));
                mB = fmaxf(mB, fmaxf(s[mt][nt][2], s[mt][nt][3]));
            }
            mA = fmaxf(mA, __shfl_xor_sync(0xffffffffu, mA, 1));
            mA = fmaxf(mA, __shfl_xor_sync(0xffffffffu, mA, 2));
            mB = fmaxf(mB, __shfl_xor_sync(0xffffffffu, mB, 1));
            mB = fmaxf(mB, __shfl_xor_sync(0xffffffffu, mB, 2));
            float sA = 0.f, sB = 0.f;
#pragma unroll
            for (int nt = 0; nt < 8; nt++) {
                float e0 = __expf(s[mt][nt][0] - mA);
                float e1 = __expf(s[mt][nt][1] - mA);
                float e2 = __expf(s[mt][nt][2] - mB);
                float e3 = __expf(s[mt][nt][3] - mB);
                sA += e0 + e1;
                sB += e2 + e3;
                p[mt][nt][0] = f22u(e0, e1);
                p[mt][nt][1] = f22u(e2, e3);
            }
            sA += __shfl_xor_sync(0xffffffffu, sA, 1);
            sA += __shfl_xor_sync(0xffffffffu, sA, 2);
            sB += __shfl_xor_sync(0xffffffffu, sB, 1);
            sB += __shfl_xor_sync(0xffffffffu, sB, 2);
            invA[mt] = 1.f / sA;
            invB[mt] = 1.f / sB;
        }
    }

    // O = P @ V  (32 x 32 output, K = 64 tokens)
    float o[2][4][4];
#pragma unroll
    for (int mt = 0; mt < 2; mt++)
#pragma unroll
        for (int nd = 0; nd < 4; nd++)
#pragma unroll
            for (int e = 0; e < 4; e++) o[mt][nd][e] = 0.f;

#pragma unroll
    for (int kt = 0; kt < 4; kt++) {
        uint32_t bv[4][2];
#pragma unroll
        for (int nd = 0; nd < 4; nd++) {
            const int d = vb + nd * 8 + qr;
            const int j0 = tokbase + kt * 16 + qc;
            __half v0 = sm[QKV_OFF + (j0    ) * QKV_STR + d];
            __half v1 = sm[QKV_OFF + (j0 + 1) * QKV_STR + d];
            __half v2 = sm[QKV_OFF + (j0 + 8) * QKV_STR + d];
            __half v3 = sm[QKV_OFF + (j0 + 9) * QKV_STR + d];
            bv[nd][0] = pack_hh(v0, v1);
            bv[nd][1] = pack_hh(v2, v3);
        }
#pragma unroll
        for (int mt = 0; mt < 2; mt++) {
            uint32_t a[4];
            a[0] = p[mt][2 * kt][0];
            a[1] = p[mt][2 * kt][1];
            a[2] = p[mt][2 * kt + 1][0];
            a[3] = p[mt][2 * kt + 1][1];
#pragma unroll
            for (int nd = 0; nd < 4; nd++) mma16816(o[mt][nd], a, bv[nd]);
        }
    }

    // write normalized O into X buffer rows [rowbase, rowbase+32)
#pragma unroll
    for (int mt = 0; mt < 2; mt++)
#pragma unroll
        for (int nd = 0; nd < 4; nd++) {
            const int rA = rowbase + mt * 16 + qr;
            const int col = h * 32 + nd * 8 + qc;
            *(uint32_t*)&sm[XS_OFF + rA * XS_STR + col] =
                f22u(o[mt][nd][0] * invA[mt], o[mt][nd][1] * invA[mt]);
            *(uint32_t*)&sm[XS_OFF + (rA + 8) * XS_STR + col] =
                f22u(o[mt][nd][2] * invB[mt], o[mt][nd][3] * invB[mt]);
        }
}

// ---------------------------------------------------------------- main kernel
__global__ void __launch_bounds__(NTHREADS, 1)
wa_main(const float* __restrict__ X, const float* __restrict__ mask,
        const float* __restrict__ b_qkv, const float* __restrict__ b_proj,
        float* __restrict__ out) {
    extern __shared__ __half sm[];
    const int tid = threadIdx.x;
    const int lane = tid & 31;
    const int w = tid >> 5;
    const int wm = w & 3, wn = w >> 2;
    const int qr = lane >> 2, qc = (lane & 3) * 2;
    const int cta = blockIdx.x;

    // ---- Phase A: load X tile [128, 192] -> smem fp16
    {
        const float4* xin = (const float4*)(X + (size_t)cta * M_TILE * C_DIM);
        for (int i = tid; i < M_TILE * 48; i += NTHREADS) {
            int row = i / 48, c4 = i % 48;
            float4 v = xin[row * 48 + c4];
            int o = XS_OFF + row * XS_STR + c4 * 4;
            *(uint32_t*)&sm[o]     = f22u(v.x, v.y);
            *(uint32_t*)&sm[o + 2] = f22u(v.z, v.w);
        }
    }

    // ---- Phase B: QKV GEMM, 9 chunks of 64 columns
    for (int chunk = 0; chunk < 9; chunk++) {
        __syncthreads();
        load_wt(sm, g_wq_t, chunk * 64);
        __syncthreads();
        float acc[2][2][4];
        gemm_128x64_k192(sm, acc);
        const int cbase = chunk * 64;
#pragma unroll
        for (int mt = 0; mt < 2; mt++)
#pragma unroll
            for (int nt = 0; nt < 2; nt++) {
                const int row = wm * 32 + mt * 16 + qr;
                const int col = cbase + wn * 16 + nt * 8 + qc;
                const float b0 = b_qkv[col], b1 = b_qkv[col + 1];
                *(uint32_t*)&sm[QKV_OFF + row * QKV_STR + col] =
                    f22u(acc[mt][nt][0] + b0, acc[mt][nt][1] + b1);
                *(uint32_t*)&sm[QKV_OFF + (row + 8) * QKV_STR + col] =
                    f22u(acc[mt][nt][2] + b0, acc[mt][nt][3] + b1);
            }
    }
    __syncthreads();

    // ---- Phase C: stage shift masks for the 2 windows
    {
        const int w0 = (cta * WPB) & (NUM_WINS - 1);
        const int w1 = (cta * WPB + 1) & (NUM_WINS - 1);
        for (int i = tid; i < 2 * 4096; i += NTHREADS) {
            int lw = i >> 12, idx = i & 4095;
            int r = idx >> 6, c = idx & 63;
            int wmask = lw ? w1 : w0;
            sm[WT_OFF + lw * (MASK_STR * 64) + r * MASK_STR + c] =
                __float2half_rn(mask[wmask * 4096 + idx]);
        }
    }
    __syncthreads();

    // ---- attention: 24 half-tile tasks over 16 warps
    // task t: pair = t >> 1 (lw = pair / 6, h = pair % 6), mhalf = t & 1
    {
        int t = w;
        attn_half(sm, (t >> 1) / N_HEADS, (t >> 1) % N_HEADS, t & 1);
        if (w < 8) {
            t = w + 16;
            attn_half(sm, (t >> 1) / N_HEADS, (t >> 1) % N_HEADS, t & 1);
        }
    }
    __syncthreads();

    // ---- Phase D: proj GEMM, 3 chunks of 64 columns -> gmem
    for (int chunk = 0; chunk < 3; chunk++) {
        __syncthreads();
        load_wt(sm, g_wp_t, chunk * 64);
        __syncthreads();
        float acc[2][2][4];
        gemm_128x64_k192(sm, acc);
        const int cbase = chunk * 64;
#pragma unroll
        for (int mt = 0; mt < 2; mt++)
#pragma unroll
            for (int nt = 0; nt < 2; nt++) {
                const int row = wm * 32 + mt * 16 + qr;
                const int col = cbase + wn * 16 + nt * 8 + qc;
                const float b0 = b_proj[col], b1 = b_proj[col + 1];
                const size_t t0 = (size_t)cta * M_TILE + row;
                float2 v0 = {acc[mt][nt][0] + b0, acc[mt][nt][1] + b1};
                float2 v1 = {acc[mt][nt][2] + b0, acc[mt][nt][3] + b1};
                *(float2*)&out[t0 * C_DIM + col]       = v0;
                *(float2*)&out[(t0 + 8) * C_DIM + col] = v1;
            }
    }
}

// ---------------------------------------------------------------- launch
extern "C" void kernel_launch(void* const* d_in, const int* in_sizes, int n_in,
                              void* d_out, int out_size) {
    const float* inputs     = (const float*)d_in[0];
    const float* mask       = (const float*)d_in[1];
    const float* w_qkv      = (const float*)d_in[2];
    const float* b_qkv      = (const float*)d_in[3];
    const float* bias_table = (const float*)d_in[4];
    const float* w_proj     = (const float*)d_in[5];
    const float* b_proj     = (const float*)d_in[6];
    float* out = (float*)d_out;

    prep_wq<<<(576 * 192 + 255) / 256, 256>>>(w_qkv);
    prep_wp<<<(192 * 192 + 255) / 256, 256>>>(w_proj);
    prep_relb<<<(N_HEADS * 64 * 64 + 255) / 256, 256>>>(bias_table);

    cudaFuncSetAttribute(wa_main, cudaFuncAttributeMaxDynamicSharedMemorySize,
                         SMEM_BYTES);
    wa_main<<<4096 / WPB, NTHREADS, SMEM_BYTES>>>(inputs, mask, b_qkv, b_proj, out);
}